// round 7
// baseline (speedup 1.0000x reference)
#include <cuda_runtime.h>
#include <cstdint>
#include <cstddef>

// SpanRepresentation: out[b, s, :] = concat(x[b,start,:], x[b,end,:], wemb[wid,:])
// B=16, L=512, D=768, W=8, WD=64, NS=4068. Spans ordered by width 1..8, then start.
//
// R7 design: one CTA stages 15 consecutive x rows in SMEM (serving start AND end
// rows for 8 widths x 8 starts), then emits each of the <=64 output rows as
// THREE 1D TMA bulk stores directly from the staged tile (3072B + 3072B + 256B).
// This removes the per-thread STG path (L1tex was co-binding with DRAM at 72%)
// and cuts L2 read traffic from ~400MB to ~46MB.

constexpr int B    = 16;
constexpr int L    = 512;
constexpr int D    = 768;
constexpr int WD   = 64;
constexpr int NS   = 4068;

constexpr int T       = 8;            // starts per tile
constexpr int TILES   = L / T;        // 64
constexpr int MAXROWS = T + 7;        // 15: rows s0 .. s0+14 cover all ends
constexpr int D4      = D / 4;        // 192 float4 per x row
constexpr int ROWB    = D * 4;        // 3072 bytes per x row
constexpr int OUTROWB = (2 * D + WD) * 4;  // 6400 bytes per output row

__device__ __forceinline__ void bulk_store(void* gmem, uint32_t smem, int bytes) {
    asm volatile("cp.async.bulk.global.shared::cta.bulk_group [%0], [%1], %2;"
                 :: "l"(gmem), "r"(smem), "r"(bytes) : "memory");
}

__global__ __launch_bounds__(256, 4)
void span_tile_kernel(const float4* __restrict__ x,      // [B, L, D/4]
                      const float4* __restrict__ wemb,   // [8, WD/4]
                      float* __restrict__ out)           // [B*NS, 1600]
{
    __shared__ float4 sx[MAXROWS * D4];   // 15*192 f4 = 46080 B
    __shared__ float4 sw[8 * WD / 4];     // 128 f4 = 2048 B   (total 48128 B)

    const int b   = blockIdx.y;
    const int s0  = blockIdx.x * T;
    const int tid = threadIdx.x;

    // ---- stage x rows [s0, s0+nrows) and wemb into SMEM (coalesced) ----
    const int nrows = min(MAXROWS, L - s0);
    const float4* xsrc = x + ((size_t)b * L + s0) * D4;
    const int nf4 = nrows * D4;
    for (int i = tid; i < nf4; i += 256) sx[i] = xsrc[i];
    for (int i = tid; i < 8 * WD / 4; i += 256) sw[i] = wemb[i];
    __syncthreads();

    // ---- each warp owns one width; lane 0 issues TMA bulk stores ----
    const int wid  = tid >> 5;    // 0..7  (width = wid+1)
    const int lane = tid & 31;

    if (lane == 0) {
        // order the generic-proxy SMEM writes before async-proxy (TMA) reads
        asm volatile("fence.proxy.async.shared::cta;" ::: "memory");

        const uint32_t sx_base = (uint32_t)__cvta_generic_to_shared(sx);
        const uint32_t sw_base = (uint32_t)__cvta_generic_to_shared(sw);

        const int w   = wid + 1;
        // cumulative span offset for this width: 512*wid - wid*(wid-1)/2
        const int off = 512 * wid - (wid * (wid - 1)) / 2;
        const uint32_t src_w = sw_base + (uint32_t)wid * (WD * 4);

        #pragma unroll
        for (int j = 0; j < T; ++j) {
            const int start = s0 + j;
            if (start > L - w) break;          // span must fit in sequence
            const size_t row = (size_t)b * NS + off + start;
            char* dst = (char*)out + row * (size_t)OUTROWB;
            const uint32_t src_s = sx_base + (uint32_t)j * ROWB;          // h_start
            const uint32_t src_e = sx_base + (uint32_t)(j + wid) * ROWB;  // h_end
            bulk_store(dst,             src_s, ROWB);   // 3072 B
            bulk_store(dst + ROWB,      src_e, ROWB);   // 3072 B
            bulk_store(dst + 2 * ROWB,  src_w, WD * 4); // 256 B
        }
        asm volatile("cp.async.bulk.commit_group;" ::: "memory");
        asm volatile("cp.async.bulk.wait_group 0;" ::: "memory");
    }
    // SMEM stays valid until every thread (incl. the waiting lane0s) exits.
}

extern "C" void kernel_launch(void* const* d_in, const int* in_sizes, int n_in,
                              void* d_out, int out_size)
{
    const float4* x    = (const float4*)d_in[0];   // [16, 512, 768] fp32
    const float4* wemb = (const float4*)d_in[1];   // [8, 64] fp32
    float* out         = (float*)d_out;            // [16, 4068, 1600] fp32

    (void)in_sizes; (void)n_in; (void)out_size;

    dim3 grid(TILES, B);   // 64 x 16 = 1024 CTAs
    dim3 block(256);
    span_tile_kernel<<<grid, block>>>(x, wemb, out);
}

// round 8
// speedup vs baseline: 1.1300x; 1.1300x over previous
#include <cuda_runtime.h>
#include <cstddef>

// SpanRepresentation: out[b, s, :] = concat(x[b,start,:], x[b,end,:], wemb[wid,:])
// B=16, L=512, D=768, W=8, WD=64, NS=4068. Spans ordered by width 1..8, then start.
//
// R8: register-broadcast scatter. One CTA per x row (b, s). Each thread loads its
// float4 of the row ONCE, then stores it to every output slot where this row
// appears: h_start of spans starting at s (widths 1..8) and h_end of spans ending
// at s (widths 1..8). wemb is written alongside the h_end visit (each output row
// has exactly one end position, so coverage is exact, no duplicates).
// x is read exactly once (25 MB); L2 traffic drops from ~817 MB (R3) to ~460 MB,
// releasing the LTS cap that was binding the write stream.

constexpr int B    = 16;
constexpr int L    = 512;
constexpr int D    = 768;
constexpr int WD   = 64;
constexpr int NS   = 4068;

constexpr int D4   = D / 4;     // 192
constexpr int WD4  = WD / 4;    // 16
constexpr int ROW4 = (2 * D + WD) / 4;  // 400 float4 per output row

__global__ __launch_bounds__(256, 8)
void span_scatter_kernel(const float4* __restrict__ x,      // [B, L, D/4]
                         const float4* __restrict__ wemb,   // [8, WD/4]
                         float4* __restrict__ out)          // [B*NS, ROW4]
{
    const int b   = blockIdx.y;
    const int s   = blockIdx.x;
    const int tid = threadIdx.x;
    const size_t base = (size_t)b * NS;

    if (tid < D4) {
        // ---- main path: warps 0..5 scatter this x row ----
        const float4 v = __ldg(&x[((size_t)b * L + s) * D4 + tid]);

        #pragma unroll
        for (int wid = 0; wid < 8; ++wid) {
            const int off = 512 * wid - (wid * (wid - 1)) / 2;  // cumulative span offset

            // as h_start of span (start=s, width=wid+1): valid if span fits
            if (s <= (L - 1) - wid) {
                const size_t row = base + off + s;
                __stcs(&out[row * ROW4 + tid], v);
            }
            // as h_end of span (end=s, start=s-wid): valid if start >= 0
            if (s >= wid) {
                const size_t row = base + off + (s - wid);
                __stcs(&out[row * ROW4 + D4 + tid], v);
            }
        }
    } else {
        // ---- wemb path: warps 6..7 (64 threads) fill the width-embedding slots
        // of the 8 output rows that END at s (one visit per output row total).
        const int t = tid - D4;              // 0..63
        #pragma unroll
        for (int p = t; p < 8 * WD4; p += 64) {   // 128 (wid, chunk) pairs
            const int wid   = p >> 4;        // 0..7
            const int chunk = p & 15;        // 0..15
            if (s >= wid) {
                const float4 wv  = __ldg(&wemb[wid * WD4 + chunk]);
                const int    off = 512 * wid - (wid * (wid - 1)) / 2;
                const size_t row = base + off + (s - wid);
                __stcs(&out[row * ROW4 + 2 * D4 + chunk], wv);
            }
        }
    }
}

extern "C" void kernel_launch(void* const* d_in, const int* in_sizes, int n_in,
                              void* d_out, int out_size)
{
    const float4* x    = (const float4*)d_in[0];   // [16, 512, 768] fp32
    const float4* wemb = (const float4*)d_in[1];   // [8, 64] fp32
    float4* out        = (float4*)d_out;           // [16, 4068, 1600] fp32

    (void)in_sizes; (void)n_in; (void)out_size;

    dim3 grid(L, B);     // 512 x 16 = 8192 CTAs, one per x row
    dim3 block(256);     // 192 scatter threads + 64 wemb threads
    span_scatter_kernel<<<grid, block>>>(x, wemb, out);
}